// round 15
// baseline (speedup 1.0000x reference)
#include <cuda_runtime.h>
#include <math.h>

#define NPASS 16
#define NFACE 640
#define NPAIR 320
#define NVERT 642
#define IMH 160
#define IMW 160
#define HW (IMH*IMW)
#define STEP (2.0f/159.0f)
#define GRID_ALL 640

// gaussian 11-tap weights (fp64 exp/normalize, rounded to float)
#define G0 1.4867195e-06f
#define G1 1.3383023e-04f
#define G2 4.4318484e-03f
#define G3 5.3990966e-02f
#define G4 2.4197073e-01f
#define G5 3.9894228e-01f
__device__ __constant__ float c_gauss[11]={G0,G1,G2,G3,G4,G5,G4,G3,G2,G1,G0};

typedef unsigned long long ull;

// packed f32x2 helpers
#define FMA2(d,a,b,c) asm("fma.rn.f32x2 %0, %1, %2, %3;" : "=l"(d) : "l"(a), "l"(b), "l"(c))
#define PK2(d,x) { unsigned _u=__float_as_uint(x); asm("mov.b64 %0, {%1,%2};" : "=l"(d) : "r"(_u), "r"(_u)); }
#define UPK(lo,hi,v) { unsigned _a,_b; asm("mov.b64 {%0,%1}, %2;" : "=r"(_a), "=r"(_b) : "l"(v)); lo=__uint_as_float(_a); hi=__uint_as_float(_b); }

// ---------------- scratch ----------------
__device__ float4 g_faceb[NPASS*NFACE*4];   // fallback path only
__device__ int    g_nvalid[NPASS];          // fallback path only
__device__ float  g_feats[NPASS*3*HW];
__device__ float  g_soft[NPASS*HW];
__device__ unsigned g_count = 0;            // persistent grid-barrier ticket

// ---------------- helpers ----------------
__device__ void quat_rod(const float* q, float scale, float* R){
    float w=q[0], x=q[1], y=q[2], z=q[3];
    float sn=sqrtf(x*x+y*y+z*z);
    float tt = 2.0f*((w<0.0f)? atan2f(-sn,-w) : atan2f(sn,w));
    float k = (sn>1e-8f)? (tt/fmaxf(sn,1e-8f)) : 2.0f;
    k *= scale;
    float ax=x*k, ay=y*k, az=z*k;
    float th=sqrtf(ax*ax+ay*ay+az*az);
    float inv=1.0f/fmaxf(th,1e-8f);
    float ux=ax*inv, uy=ay*inv, uz=az*inv;
    float s=sinf(th), c=cosf(th), cc=1.0f-c;
    R[0]=1.0f+cc*(-(uy*uy+uz*uz)); R[1]=-s*uz+cc*(ux*uy);          R[2]= s*uy+cc*(ux*uz);
    R[3]= s*uz+cc*(ux*uy);         R[4]=1.0f+cc*(-(ux*ux+uz*uz));  R[5]=-s*ux+cc*(uy*uz);
    R[6]=-s*uy+cc*(ux*uz);         R[7]= s*ux+cc*(uy*uz);          R[8]=1.0f+cc*(-(ux*ux+uy*uy));
}

__device__ void compute_RT(int p, const float* quat, const float* trans,
                           float* sR, float* sT){
    int f=p>>3, st=p&7;
    float R[9], Rs[9];
    quat_rod(&quat[(f*2+1)*4], 1.0f, R);
    quat_rod(&quat[(f*2+0)*4], 1.0f/16.0f, Rs);
    for(int s=0;s<st;s++){
        float Rn[9];
        for(int a=0;a<3;a++)
            for(int b=0;b<3;b++)
                Rn[a*3+b]=R[a*3+0]*Rs[0*3+b]+R[a*3+1]*Rs[1*3+b]+R[a*3+2]*Rs[2*3+b];
        for(int k=0;k<9;k++) R[k]=Rn[k];
    }
    for(int k=0;k<9;k++) sR[k]=R[k];
    float ti=(float)st*(1.0f/7.0f);
    for(int k=0;k<3;k++)
        sT[k]=trans[(f*2+1)*3+k] + ti*trans[(f*2+0)*3+k] - ((k==2)?2.0f:0.0f);
}

// transform one vertex (same op order as the sv path: R rows then +T)
__device__ __forceinline__ void xform(const float* uv, const float* R, const float* T,
                                      int n, float& vx, float& vy, float& vz){
    float ux=uv[n*3+0], uy=uv[n*3+1], uz=uv[n*3+2];
    vx=R[0]*ux+R[1]*uy+R[2]*uz + T[0];
    vy=R[3]*ux+R[4]*uy+R[5]*uz + T[1];
    vz=R[6]*ux+R[7]*uy+R[8]*uz + T[2];
}

// face record from gmem verts; z-plane coeffs (Za,Zb,Zc) in .w lanes
__device__ __forceinline__ bool face_record_g(const float* uv, const float* R, const float* T,
                                              const int* faces, int i,
                                              float4& r0, float4& r1, float4& r2){
    int i0=faces[i*3+0], i1=faces[i*3+1], i2=faces[i*3+2];
    float ax3,ay3,az3, bx3,by3,bz3, cx3,cy3,cz3;
    xform(uv,R,T,i0,ax3,ay3,az3);
    xform(uv,R,T,i1,bx3,by3,bz3);
    xform(uv,R,T,i2,cx3,cy3,cz3);
    float nz=(bx3-ax3)*(cy3-ay3)-(by3-ay3)*(cx3-ax3);
    const float F=(float)(1.0/tan(1.57/4.0));   // exact reference focal (NOT pi/8)
    float ax=(ax3*F)/(-az3), ay=(ay3*F)/(-az3);
    float bx=(bx3*F)/(-bz3), by=(by3*F)/(-bz3);
    float cx=(cx3*F)/(-cz3), cy=(cy3*F)/(-cz3);
    float denom=(bx-ax)*(cy-ay)-(by-ay)*(cx-ax);
    bool valid=(nz>0.0f)&&(fabsf(denom)>1e-9f);
    if(valid){
        float inv=1.0f/denom;
        float A0=(bx*cy-by*cx)*inv, B0=(by-cy)*inv, C0=(cx-bx)*inv;
        float A1=(cx*ay-cy*ax)*inv, B1=(cy-ay)*inv, C1=(ax-cx)*inv;
        float A2=(ax*by-ay*bx)*inv, B2=(ay-by)*inv, C2=(bx-ax)*inv;
        float Za=A0*az3+A1*bz3+A2*cz3;
        float Zb=B0*az3+B1*bz3+B2*cz3;
        float Zc=C0*az3+C1*bz3+C2*cz3;
        r0=make_float4(A0,B0,C0,Za);
        r1=make_float4(A1,B1,C1,Zb);
        r2=make_float4(A2,B2,C2,Zc);
    }
    return valid;
}

// store face record 'pos' into pair-interleaved SoA layout.
__device__ __forceinline__ void store_face(float* fv, int pos,
                                           float4 r0, float4 r1, float4 r2){
    int h=pos>>1, o=pos&1, b=h*4+o;
    fv[0*4*NPAIR+b]=r0.x;  fv[0*4*NPAIR+b+2]=r0.y;
    fv[1*4*NPAIR+b]=r0.z;  fv[1*4*NPAIR+b+2]=r1.x;
    fv[2*4*NPAIR+b]=r1.y;  fv[2*4*NPAIR+b+2]=r1.z;
    fv[3*4*NPAIR+b]=r2.x;  fv[3*4*NPAIR+b+2]=r2.y;
    fv[4*4*NPAIR+b]=r2.z;  fv[4*4*NPAIR+b+2]=r0.w;
    fv[5*4*NPAIR+b]=r1.w;  fv[5*4*NPAIR+b+2]=r2.w;
}

// ---------------- raster pixel loop over packed pair layout (16B-aligned fv) ----------------
__device__ void raster_pixels(const float* fv, const int* sid, int m,
                              int p, int y0, int tx, int ty,
                              const float* __restrict__ ffeat){
    int y=y0+ty;
    float pyv = 1.0f - (float)y*STEP;
    float px0 = fmaf((float)tx, STEP, -1.0f);
    float pxs[5];
    #pragma unroll
    for(int i=0;i<5;i++) pxs[i]=px0+(32.0f*STEP)*(float)i;
    ull px2[5], pyv2;
    #pragma unroll
    for(int i=0;i<5;i++) PK2(px2[i], pxs[i]);
    PK2(pyv2, pyv);

    float mm[5], bzv[5]; int biv[5];
    #pragma unroll
    for(int i=0;i<5;i++){ mm[i]=-3.0e38f; bzv[i]=-1e9f; biv[i]=-1; }

    int mp=(m+1)>>1;
    const ulonglong2* V0=(const ulonglong2*)(fv+0*4*NPAIR);
    const ulonglong2* V1=(const ulonglong2*)(fv+1*4*NPAIR);
    const ulonglong2* V2=(const ulonglong2*)(fv+2*4*NPAIR);
    const ulonglong2* V3=(const ulonglong2*)(fv+3*4*NPAIR);
    const ulonglong2* V4=(const ulonglong2*)(fv+4*4*NPAIR);
    const ulonglong2* V5=(const ulonglong2*)(fv+5*4*NPAIR);

    for(int h=0; h<mp; h++){
        ulonglong2 q0=V0[h], q1=V1[h], q2=V2[h], q3=V3[h], q4=V4[h], q5=V5[h];
        ull w0b,w1b,w2b,zbp;
        FMA2(w0b, q1.x, pyv2, q0.x);
        FMA2(w1b, q2.y, pyv2, q1.y);
        FMA2(w2b, q4.x, pyv2, q3.x);
        FMA2(zbp, q5.y, pyv2, q4.y);
        #pragma unroll
        for(int i=0;i<5;i++){
            ull w0,w1,w2,zz;
            FMA2(w0, q0.y, px2[i], w0b);
            FMA2(w1, q2.x, px2[i], w1b);
            FMA2(w2, q3.y, px2[i], w2b);
            FMA2(zz, q5.x, px2[i], zbp);
            float w0f,w0g,w1f,w1g,w2f,w2g,zf,zg;
            UPK(w0f,w0g,w0); UPK(w1f,w1g,w1); UPK(w2f,w2g,w2); UPK(zf,zg,zz);
            float mnf=fminf(w0f,fminf(w1f,w2f));
            float mng=fminf(w0g,fminf(w1g,w2g));
            mm[i]=fmaxf(mm[i],fmaxf(mnf,mng));
            if(mnf>=-1e-6f && zf>bzv[i]){ bzv[i]=zf; biv[i]=2*h; }
            if(mng>=-1e-6f && zg>bzv[i]){ bzv[i]=zg; biv[i]=2*h+1; }
        }
    }

    #pragma unroll
    for(int i=0;i<5;i++){
        int x=tx+32*i;
        float soft=1.0f/(1.0f+expf(-7000.0f*mm[i]));
        g_soft[p*HW + y*IMW + x]=soft;
        float f0=0.f,f1=0.f,f2=0.f;
        if(biv[i]>=0){
            int pos=biv[i], hh=pos>>1, b=(hh*4)+(pos&1);
            float A0=fv[b],            B0=fv[b+2];
            float C0=fv[1*4*NPAIR+b],  A1=fv[1*4*NPAIR+b+2];
            float B1=fv[2*4*NPAIR+b],  C1=fv[2*4*NPAIR+b+2];
            float A2=fv[3*4*NPAIR+b],  B2=fv[3*4*NPAIR+b+2];
            float C2=fv[4*4*NPAIR+b];
            float pxv=fmaf((float)x, STEP, -1.0f);
            float w0=fmaf(B0,pxv,fmaf(C0,pyv,A0));
            float w1=fmaf(B1,pxv,fmaf(C1,pyv,A1));
            float w2=fmaf(B2,pxv,fmaf(C2,pyv,A2));
            const float* ff=&ffeat[sid[pos]*9];
            f0=w0*ff[0]+w1*ff[3]+w2*ff[6];
            f1=w0*ff[1]+w1*ff[4]+w2*ff[7];
            f2=w0*ff[2]+w1*ff[5]+w2*ff[8];
        }
        int bo=p*3*HW + y*IMW + x;
        g_feats[bo      ]=f0;
        g_feats[bo+  HW ]=f1;
        g_feats[bo+2*HW ]=f2;
    }
}

// ---------------- post task: 8-row tile, rgb blur (t<960) or mask chain ----------------
__device__ void post_task8(float* bufA, float* bufB, int t,
                           float* __restrict__ out, int tid, int nt){
    if(t<960){
        int img=t/20, tile=t%20, y0=tile*8;
        const float* in=&g_feats[img*HW];
        for(int idx=tid; idx<18*160; idx+=nt){
            int r=idx/160, x=idx%160;
            int yy=y0-5+r;
            yy = yy<0 ? -yy : (yy>IMH-1 ? 2*(IMH-1)-yy : yy);
            bufA[idx]=in[yy*IMW+x];
        }
        __syncthreads();
        for(int idx=tid; idx<8*160; idx+=nt){
            int j=idx/160, x=idx%160;
            float acc=0.f;
            #pragma unroll
            for(int k=0;k<11;k++) acc += c_gauss[k]*bufA[(j+k)*160+x];
            bufB[idx]=acc;
        }
        __syncthreads();
        int p=img/3, c=img%3;
        float* o=&out[(p*4+c)*HW];
        for(int idx=tid; idx<8*160; idx+=nt){
            int j=idx/160, x=idx%160;
            float acc=0.f;
            #pragma unroll
            for(int k=0;k<11;k++){
                int xx=x+k-5;
                xx = xx<0 ? -xx : (xx>IMW-1 ? 2*(IMW-1)-xx : xx);
                acc += c_gauss[k]*bufB[j*160+xx];
            }
            o[(y0+j)*IMW+x]=acc;
        }
    } else {
        int mt=t-960;
        int p=mt/20, tile=mt%20, y0=tile*8;
        const float* in=&g_soft[p*HW];
        for(int idx=tid; idx<30*160; idx+=nt){
            int r=idx/160, x=idx%160;
            int yy=y0-11+r;
            if(yy>=0 && yy<IMH) bufA[idx]=in[yy*IMW+x];
        }
        __syncthreads();
        for(int idx=tid; idx<28*160; idx+=nt){
            int r=idx/160, x=idx%160;
            int yy=y0-10+r;
            if(yy<0 || yy>=IMH) continue;
            float mval=3.4e38f;
            #pragma unroll
            for(int dy=-1;dy<=1;dy++){
                int ry=yy+dy; if(ry<0||ry>=IMH) continue;
                int sr=ry-(y0-11);
                #pragma unroll
                for(int dx=-1;dx<=1;dx++){
                    int xx=x+dx; if(xx<0||xx>=IMW) continue;
                    mval=fminf(mval, bufA[sr*160+xx]);
                }
            }
            bufB[idx]=mval;
        }
        __syncthreads();
        for(int idx=tid; idx<18*160; idx+=nt){
            int r=idx/160, x=idx%160;
            int yb=y0-5+r;
            if(yb<0 || yb>=IMH) continue;
            float acc=0.f;
            #pragma unroll
            for(int k=0;k<11;k++){
                int yy=yb+k-5;
                yy = yy<0 ? -yy : (yy>IMH-1 ? 2*(IMH-1)-yy : yy);
                acc += c_gauss[k]*bufB[(yy-(y0-10))*160+x];
            }
            bufA[idx]=acc;
        }
        __syncthreads();
        for(int idx=tid; idx<18*160; idx+=nt){
            int r=idx/160, x=idx%160;
            int yb=y0-5+r;
            if(yb<0 || yb>=IMH) continue;
            float acc=0.f;
            #pragma unroll
            for(int k=0;k<11;k++){
                int xx=x+k-5;
                xx = xx<0 ? -xx : (xx>IMW-1 ? 2*(IMW-1)-xx : xx);
                acc += c_gauss[k]*bufA[r*160+xx];
            }
            bufB[idx]=acc;
        }
        __syncthreads();
        for(int idx=tid; idx<8*160; idx+=nt){
            int j=idx/160, x=idx%160;
            int yb=y0+j;
            float acc=0.f;
            #pragma unroll
            for(int k=0;k<11;k++){
                int yy=yb+k-5;
                yy = yy<0 ? -yy : (yy>IMH-1 ? 2*(IMH-1)-yy : yy);
                acc += c_gauss[k]*bufB[(yy-(y0-5))*160+x];
            }
            bufA[idx]=acc;
        }
        __syncthreads();
        float* o=&out[(p*4+3)*HW];
        for(int idx=tid; idx<8*160; idx+=nt){
            int j=idx/160, x=idx%160;
            float acc=0.f;
            #pragma unroll
            for(int k=0;k<11;k++){
                int xx=x+k-5;
                xx = xx<0 ? -xx : (xx>IMW-1 ? 2*(IMW-1)-xx : xx);
                acc += c_gauss[k]*bufA[j*160+xx];
            }
            o[(y0+j)*IMW+x]=acc;
        }
    }
}

// ---------------- unified single-launch kernel: 640 blocks x 128 threads ----------------
struct __align__(16) GeomRaster {
    float  fv[6*4*NPAIR];          // 30720 B, at offset 0 (LDS.128 alignment)
    int    sid[NFACE+2];
    float  R[9], T[3];
    int    warp_cnt[4], warp_off[4], chunk_base;
};
struct __align__(16) Post8 { float bufA[30*160]; float bufB[28*160]; };
union __align__(16) UShared { GeomRaster g; Post8 p; };

__global__ void __launch_bounds__(128,5) k_all(const float* __restrict__ uv,
                                               const int* __restrict__ faces,
                                               const float* __restrict__ quat,
                                               const float* __restrict__ trans,
                                               const float* __restrict__ ffeat,
                                               float* __restrict__ out){
    __shared__ UShared u;
    int bx=blockIdx.x;
    int p=bx/40, band=bx%40, y0=band*4;
    int tid=threadIdx.x;
    int lane=tid&31, wid=tid>>5;

    // ---- phase 1: rotation/translation + face records (verts from GMEM) ----
    if(tid==0){
        compute_RT(p, quat, trans, u.g.R, u.g.T);
        u.g.chunk_base=0;
    }
    __syncthreads();

    float pyc = 1.0f - ((float)y0+1.5f)*STEP;
    float pyr = 1.5f*STEP + 1e-4f;
    const float TAU = -0.002f;

    for(int base=0; base<NFACE; base+=128){
        int fidx=base+tid;
        bool keep=false;
        float4 r0,r1,r2;
        if(face_record_g(uv, u.g.R, u.g.T, faces, fidx, r0, r1, r2)){
            float u0=r0.x + fabsf(r0.y) + r0.z*pyc + fabsf(r0.z)*pyr;
            float u1=r1.x + fabsf(r1.y) + r1.z*pyc + fabsf(r1.z)*pyr;
            float u2=r2.x + fabsf(r2.y) + r2.z*pyc + fabsf(r2.z)*pyr;
            keep = fminf(u0,fminf(u1,u2)) >= TAU;
        }
        unsigned bal=__ballot_sync(0xffffffffu, keep);
        if(lane==0) u.g.warp_cnt[wid]=__popc(bal);
        __syncthreads();
        if(tid==0){
            int a=u.g.chunk_base;
            for(int w=0;w<4;w++){ u.g.warp_off[w]=a; a+=u.g.warp_cnt[w]; }
            u.g.chunk_base=a;
        }
        __syncthreads();
        if(keep){
            int pos=u.g.warp_off[wid]+__popc(bal&((1u<<lane)-1u));
            store_face(u.g.fv, pos, r0, r1, r2);
            u.g.sid[pos]=fidx;
        }
        __syncthreads();
    }
    int m=u.g.chunk_base;
    if(tid==0 && (m&1)){
        float4 s0=make_float4(-1e9f,0.f,0.f,0.f);
        store_face(u.g.fv, m, s0, s0, s0);
        u.g.sid[m]=0;
    }
    __syncthreads();

    // ---- phase 2: raster (warp wid owns row y0+wid) ----
    raster_pixels(u.g.fv, u.g.sid, m, p, y0, lane, wid, ffeat);

    // ---- grid barrier (640 blocks co-resident: 5/SM via launch_bounds) ----
    __syncthreads();
    __threadfence();
    if(tid==0){
        unsigned arrival=atomicAdd(&g_count, 1u);
        unsigned target=(arrival/GRID_ALL + 1u)*GRID_ALL;
        while(*((volatile unsigned*)&g_count) < target) __nanosleep(32);
    }
    __syncthreads();

    // ---- phase 3: post (2 tasks of 1280) ----
    for(int t=bx; t<1280; t+=GRID_ALL){
        __syncthreads();
        post_task8(u.p.bufA, u.p.bufB, t, out, tid, 128);
    }
}

// ================= fallback 3-kernel path =================
__global__ void __launch_bounds__(640) k_geom(const float* __restrict__ uv,
                                              const int* __restrict__ faces,
                                              const float* __restrict__ quat,
                                              const float* __restrict__ trans){
    int p=blockIdx.x; int i=threadIdx.x;
    __shared__ float sR[9], sT[3];
    __shared__ int wcnt[20], wbase[20];
    if(i==0) compute_RT(p, quat, trans, sR, sT);
    __syncthreads();
    int lane=i&31, wid=i>>5;
    float4 r0,r1,r2;
    bool valid=face_record_g(uv, sR, sT, faces, i, r0, r1, r2);
    unsigned bal=__ballot_sync(0xffffffffu, valid);
    if(lane==0) wcnt[wid]=__popc(bal);
    __syncthreads();
    if(i==0){
        int acc=0;
        for(int w=0;w<20;w++){ wbase[w]=acc; acc+=wcnt[w]; }
        g_nvalid[p]=acc;
    }
    __syncthreads();
    if(valid){
        int pos=wbase[wid]+__popc(bal&((1u<<lane)-1u));
        float4* rec=&g_faceb[(p*NFACE+pos)*4];
        rec[0]=r0; rec[1]=r1; rec[2]=r2;
        rec[3]=make_float4(__int_as_float(i), 0.f, 0.f, 0.f);
    }
}

__global__ void __launch_bounds__(256) k_raster_fb(const float* __restrict__ ffeat){
    int p=blockIdx.z;
    int y0=blockIdx.y*8;
    int tx=threadIdx.x;
    int tid=threadIdx.y*32+tx;

    __shared__ __align__(16) float fv[6*4*NPAIR];
    __shared__ int   sid[NFACE+2];

    int n=g_nvalid[p];
    const float4* src=&g_faceb[p*NFACE*4];
    for(int i=tid;i<n;i+=256){
        store_face(fv, i, src[4*i+0], src[4*i+1], src[4*i+2]);
        sid[i]=__float_as_int(src[4*i+3].x);
    }
    if(tid==0 && (n&1)){
        float4 s0=make_float4(-1e9f,0.f,0.f,0.f);
        store_face(fv, n, s0, s0, s0);
        sid[n]=0;
    }
    __syncthreads();
    raster_pixels(fv, sid, n, p, y0, tx, threadIdx.y, ffeat);
}

__global__ void __launch_bounds__(128) k_post_fb(float* __restrict__ out){
    __shared__ __align__(16) float bufA[30*160];
    __shared__ __align__(16) float bufB[28*160];
    post_task8(bufA, bufB, blockIdx.x, out, threadIdx.x, 128);
}

// ---------------- launch ----------------
extern "C" void kernel_launch(void* const* d_in, const int* in_sizes, int n_in,
                              void* d_out, int out_size) {
    const float* trans=(const float*)d_in[0];
    const float* quat =(const float*)d_in[1];
    const float* uv   =(const float*)d_in[2];
    const float* ffeat=(const float*)d_in[3];
    const int*   faces=(const int*)  d_in[4];
    float* out=(float*)d_out;

    int dev=0; cudaGetDevice(&dev);
    int nsm=0; cudaDeviceGetAttribute(&nsm, cudaDevAttrMultiProcessorCount, dev);
    int per_sm=0;
    cudaOccupancyMaxActiveBlocksPerMultiprocessor(&per_sm, k_all, 128, 0);
    if((long)per_sm*nsm >= GRID_ALL){
        k_all<<<GRID_ALL, 128>>>(uv, faces, quat, trans, ffeat, out);
    } else {
        k_geom<<<NPASS, 640>>>(uv, faces, quat, trans);
        k_raster_fb<<<dim3(1,20,NPASS), dim3(32,8)>>>(ffeat);
        k_post_fb<<<1280, 128>>>(out);
    }
}